// round 1
// baseline (speedup 1.0000x reference)
#include <cuda_runtime.h>

// INLWT inverse lifting wavelet transform, fused one-pass.
//
// Reference math:
//   y = P2U2 @ [A,B,C,D]  (per-pixel 4-vec), then circular rolls of rows 1,2,3
//   z = (P1U1/4) @ y_rolled, then 2x2 depth-to-space.
// Fused as a gather: output block (i,j) pulls
//   y0 from (i,j), y1 from (i-1,j), y2 from (i,j-1), y3 from (i-1,j-1)
// with circular wrap, applies both 4x4 matrices in registers, writes two
// float2 rows of the 2x2 output block.

#define H1 256
#define W1 256

__global__ void inlwt_kernel(const float* __restrict__ A,
                             const float* __restrict__ B,
                             const float* __restrict__ C,
                             const float* __restrict__ D,
                             float* __restrict__ out)
{
    const int j  = threadIdx.x;          // 0..W1-1
    const int i  = blockIdx.x;           // 0..H1-1
    const int bc = blockIdx.y;           // 0..b*c-1

    const size_t plane = (size_t)H1 * W1;
    const size_t base  = (size_t)bc * plane;

    const int im1 = (i == 0) ? (H1 - 1) : (i - 1);
    const int jm1 = (j == 0) ? (W1 - 1) : (j - 1);

    const size_t i00 = base + (size_t)i   * W1 + j;    // (i, j)
    const size_t i01 = base + (size_t)i   * W1 + jm1;  // (i, j-1)
    const size_t i10 = base + (size_t)im1 * W1 + j;    // (i-1, j)
    const size_t i11 = base + (size_t)im1 * W1 + jm1;  // (i-1, j-1)

    // 16 independent loads -> MLP ~16, latency hidden.
    const float a00 = A[i00], b00 = B[i00], c00 = C[i00], d00 = D[i00];
    const float a10 = A[i10], b10 = B[i10], c10 = C[i10], d10 = D[i10];
    const float a01 = A[i01], b01 = B[i01], c01 = C[i01], d01 = D[i01];
    const float a11 = A[i11], b11 = B[i11], c11 = C[i11], d11 = D[i11];

    // P2 @ U2 rows (row k applied at the gathered position for y_k)
    const float y0 =  1.3066f * a00 + (-0.5412f) * b00 + (-0.4671f) * c00 +   1.3349f  * d00;
    const float y1 =  0.5412f * a10 +   1.3066f  * b10 + (-1.3349f) * c10 + (-0.4671f) * d10;
    const float y2 =  0.5412f * a01 +   1.3066f  * b01 +   1.3349f  * c01 +   0.4671f  * d01;
    const float y3 =  1.3066f * a11 + (-0.5412f) * b11 +   0.4671f  * c11 + (-1.3349f) * d11;

    // (P1 @ U1) / 4
    const float z0 =   0.2281f  * y0 +   0.0064f  * y1 + (-0.1021f) * y2 +   0.0029f  * y3;
    const float z1 = (-0.0064f) * y0 +   0.2281f  * y1 +   0.0029f  * y2 +   0.1021f  * y3;
    const float z2 =   0.1021f  * y0 +   0.0029f  * y1 +   0.2281f  * y2 + (-0.0064f) * y3;
    const float z3 =   0.0029f  * y0 + (-0.1021f) * y1 +   0.0064f  * y2 +   0.2281f  * y3;

    // 2x2 depth-to-space: out[2i + y][2j + x] = z[2y + x]
    const int H = 2 * H1, W = 2 * W1;
    float* orow0 = out + (size_t)bc * H * W + (size_t)(2 * i)     * W + 2 * j;
    float* orow1 = out + (size_t)bc * H * W + (size_t)(2 * i + 1) * W + 2 * j;
    *reinterpret_cast<float2*>(orow0) = make_float2(z0, z1);
    *reinterpret_cast<float2*>(orow1) = make_float2(z2, z3);
}

extern "C" void kernel_launch(void* const* d_in, const int* in_sizes, int n_in,
                              void* d_out, int out_size)
{
    const float* A = (const float*)d_in[0];
    const float* B = (const float*)d_in[1];
    const float* C = (const float*)d_in[2];
    const float* D = (const float*)d_in[3];
    float* out = (float*)d_out;

    const int bc = in_sizes[0] / (H1 * W1);  // b*c = 256 for the given shapes

    dim3 grid(H1, bc);
    dim3 block(W1);
    inlwt_kernel<<<grid, block>>>(A, B, C, D, out);
}

// round 3
// speedup vs baseline: 1.3564x; 1.3564x over previous
#include <cuda_runtime.h>

// INLWT inverse lifting wavelet transform — fused one-pass, float4-vectorized.
// Each thread computes 4 adjacent output 2x2 blocks (4 consecutive j positions).
// j-1 neighbor terms flow through registers + __shfl_up; only lane 0 of each
// warp reloads the boundary element (8 predicated scalar loads).

#define H1 256
#define W1 256

__global__ void __launch_bounds__(256) inlwt_kernel(
    const float* __restrict__ A,
    const float* __restrict__ B,
    const float* __restrict__ C,
    const float* __restrict__ D,
    float* __restrict__ out)
{
    const int tid  = threadIdx.x;
    const int rowb = tid >> 6;          // 0..3 : row within block
    const int x    = tid & 63;          // 0..63 : pixel-group within row
    const int lane = tid & 31;

    const int i  = blockIdx.x * 4 + rowb;   // 0..H1-1
    const int bc = blockIdx.y;

    const size_t plane = (size_t)H1 * W1;
    const size_t base  = (size_t)bc * plane;

    const int im1 = (i == 0) ? (H1 - 1) : (i - 1);
    const int j0  = x << 2;                 // 0,4,...,252

    const size_t o_cur = base + (size_t)i   * W1 + j0;
    const size_t o_up  = base + (size_t)im1 * W1 + j0;

    // 8 x LDG.128 — fully coalesced, MLP=8 per thread.
    const float4 aC = *reinterpret_cast<const float4*>(A + o_cur);
    const float4 bC = *reinterpret_cast<const float4*>(B + o_cur);
    const float4 cC = *reinterpret_cast<const float4*>(C + o_cur);
    const float4 dC = *reinterpret_cast<const float4*>(D + o_cur);
    const float4 aU = *reinterpret_cast<const float4*>(A + o_up);
    const float4 bU = *reinterpret_cast<const float4*>(B + o_up);
    const float4 cU = *reinterpret_cast<const float4*>(C + o_up);
    const float4 dU = *reinterpret_cast<const float4*>(D + o_up);

    // P2@U2 rows applied at each of this thread's 4 positions.
    // y0 (row0, at (i,j)) and r2 (row2, at (i,j)) from current row;
    // y1 (row1, at (i-1,j)) and r3 (row3, at (i-1,j)) from row i-1.
    float y0[4], y1[4], r2[4], r3[4];
    {
        const float ax[4] = {aC.x, aC.y, aC.z, aC.w};
        const float bx[4] = {bC.x, bC.y, bC.z, bC.w};
        const float cx[4] = {cC.x, cC.y, cC.z, cC.w};
        const float dx[4] = {dC.x, dC.y, dC.z, dC.w};
        const float au[4] = {aU.x, aU.y, aU.z, aU.w};
        const float bu[4] = {bU.x, bU.y, bU.z, bU.w};
        const float cu[4] = {cU.x, cU.y, cU.z, cU.w};
        const float du[4] = {dU.x, dU.y, dU.z, dU.w};
        #pragma unroll
        for (int p = 0; p < 4; ++p) {
            y0[p] =  1.3066f * ax[p] + (-0.5412f) * bx[p] + (-0.4671f) * cx[p] +   1.3349f  * dx[p];
            r2[p] =  0.5412f * ax[p] +   1.3066f  * bx[p] +   1.3349f  * cx[p] +   0.4671f  * dx[p];
            y1[p] =  0.5412f * au[p] +   1.3066f  * bu[p] + (-1.3349f) * cu[p] + (-0.4671f) * du[p];
            r3[p] =  1.3066f * au[p] + (-0.5412f) * bu[p] +   0.4671f  * cu[p] + (-1.3349f) * du[p];
        }
    }

    // Neighbor's last r2/r3 (pixel j0-1). Lanes 1..31 via shfl; lane 0 reloads.
    float r2m = __shfl_up_sync(0xFFFFFFFFu, r2[3], 1);
    float r3m = __shfl_up_sync(0xFFFFFFFFu, r3[3], 1);
    if (lane == 0) {
        const int jm1 = (j0 == 0) ? (W1 - 1) : (j0 - 1);
        const size_t p0 = base + (size_t)i   * W1 + jm1;
        const size_t p1 = base + (size_t)im1 * W1 + jm1;
        r2m = 0.5412f * A[p0] +   1.3066f  * B[p0] + 1.3349f * C[p0] +   0.4671f  * D[p0];
        r3m = 1.3066f * A[p1] + (-0.5412f) * B[p1] + 0.4671f * C[p1] + (-1.3349f) * D[p1];
    }

    // z = (P1@U1)/4 applied to (y0, y1, y2, y3) where y2/y3 are shifted r2/r3.
    float z0[4], z1[4], z2[4], z3[4];
    #pragma unroll
    for (int p = 0; p < 4; ++p) {
        const float v2 = (p == 0) ? r2m : r2[p - 1];
        const float v3 = (p == 0) ? r3m : r3[p - 1];
        z0[p] =   0.2281f  * y0[p] +   0.0064f  * y1[p] + (-0.1021f) * v2 +   0.0029f  * v3;
        z1[p] = (-0.0064f) * y0[p] +   0.2281f  * y1[p] +   0.0029f  * v2 +   0.1021f  * v3;
        z2[p] =   0.1021f  * y0[p] +   0.0029f  * y1[p] +   0.2281f  * v2 + (-0.0064f) * v3;
        z3[p] =   0.0029f  * y0[p] + (-0.1021f) * y1[p] +   0.0064f  * v2 +   0.2281f  * v3;
    }

    // 2x2 depth-to-space: out[2i][2j+0..1] = z0,z1 ; out[2i+1][2j+0..1] = z2,z3.
    // 4 pixels -> 8 contiguous floats per output row -> 2 x STG.128 per row.
    const int W = 2 * W1;
    float* orow0 = out + (size_t)bc * (2 * H1) * W + (size_t)(2 * i)     * W + 2 * j0;
    float* orow1 = out + (size_t)bc * (2 * H1) * W + (size_t)(2 * i + 1) * W + 2 * j0;
    reinterpret_cast<float4*>(orow0)[0] = make_float4(z0[0], z1[0], z0[1], z1[1]);
    reinterpret_cast<float4*>(orow0)[1] = make_float4(z0[2], z1[2], z0[3], z1[3]);
    reinterpret_cast<float4*>(orow1)[0] = make_float4(z2[0], z3[0], z2[1], z3[1]);
    reinterpret_cast<float4*>(orow1)[1] = make_float4(z2[2], z3[2], z2[3], z3[3]);
}

extern "C" void kernel_launch(void* const* d_in, const int* in_sizes, int n_in,
                              void* d_out, int out_size)
{
    const float* A = (const float*)d_in[0];
    const float* B = (const float*)d_in[1];
    const float* C = (const float*)d_in[2];
    const float* D = (const float*)d_in[3];
    float* out = (float*)d_out;

    const int bc = in_sizes[0] / (H1 * W1);  // b*c

    dim3 grid(H1 / 4, bc);   // block covers 4 rows of one channel plane
    dim3 block(256);
    inlwt_kernel<<<grid, block>>>(A, B, C, D, out);
}